// round 3
// baseline (speedup 1.0000x reference)
#include <cuda_runtime.h>

// ProteinCRF: batched linear-chain CRF negative log-likelihood.
// B=2048 sequences, L=2048 steps, T=8 tags.
//
// Inputs (metadata order):
//   d_in[0] emissions         float32 [B, L, T]
//   d_in[1] transitions       float32 [T, T]
//   d_in[2] start_transitions float32 [T]
//   d_in[3] end_transitions   float32 [T]
//   d_in[4] tags              int64 OR int32 [B, L] (0 = pad, 1..T = tag+1)
//                             -- width detected on device, see below
// Output: scalar float32 = mean(denom - num)
//
// Denominator (log partition) via exp-domain scan:
//   beta' = (E^T beta) .* exp(em_t),  E = exp(transitions) elementwise,
// renormalized by a power of two every 4 steps (exponent accumulated in an
// int; no MUFU in the renorm). Final: denom = m0 + eacc*ln2 + log(sum).
//
// Mapping: 8 lanes per batch (one per state); 8x8 matvec via intra-group
// shuffles.
//
// Tag-width detection: lengths >= L/2, so tags[0][1] != 0. If the buffer is
// int64 (LE), 32-bit word #1 is the HIGH word of element 0 -> 0. If int32,
// word #1 is tags[0][1] -> nonzero. So: stride = (word1 == 0) ? 2 : 1.

#define CRF_B 2048
#define CRF_L 2048
#define CRF_T 8

__device__ float g_llh[CRF_B];   // per-batch (denom - num)

__global__ __launch_bounds__(128, 1)
void crf_forward_kernel(const float* __restrict__ emissions,
                        const float* __restrict__ transitions,
                        const float* __restrict__ start_tr,
                        const float* __restrict__ end_tr,
                        const int*   __restrict__ tagsw)   // 32-bit word view of tags
{
    __shared__ float s_trans[CRF_T * CRF_T];
    __shared__ float s_start[CRF_T];
    __shared__ float s_end[CRF_T];

    int tid = threadIdx.x;
    if (tid < CRF_T * CRF_T) s_trans[tid] = transitions[tid];
    if (tid >= 64 && tid < 64 + CRF_T) s_start[tid - 64] = start_tr[tid - 64];
    if (tid >= 72 && tid < 72 + CRF_T) s_end[tid - 72]   = end_tr[tid - 72];
    __syncthreads();

    // ---- tag element width detection (uniform across grid, cached in L2) ----
    const int tstride = (tagsw[1] == 0) ? 2 : 1;   // 2 words if int64, 1 if int32

    const int lane  = tid & 31;
    const int g     = lane & 24;        // 8-lane group base within warp
    const int j     = lane & 7;         // my state
    const unsigned gmask = 0xFFu << g;  // my group's lanes

    const int batch = (blockIdx.x * blockDim.x + tid) >> 3;

    // Column j of E = exp(transitions): Ecol[i] = exp(trans[i][j])
    float Ecol[CRF_T];
#pragma unroll
    for (int i = 0; i < CRF_T; i++) Ecol[i] = __expf(s_trans[i * CRF_T + j]);

    const float* em_base = emissions + (size_t)batch * CRF_L * CRF_T;
    const int*   tg_base = tagsw + (size_t)batch * CRF_L * tstride;

    // ---- t = 0 ----
    float em  = em_base[j];
    int   tag = tg_base[0];           // low word (LE) == value for small ints
    int   cur = tag - 1;

    float a0 = s_start[j] + em;
    float mx = a0;
    mx = fmaxf(mx, __shfl_xor_sync(gmask, mx, 1, 8));
    mx = fmaxf(mx, __shfl_xor_sync(gmask, mx, 2, 8));
    mx = fmaxf(mx, __shfl_xor_sync(gmask, mx, 4, 8));
    const float m0 = mx;

    float beta = __expf(a0 - m0);
    int   eacc = 0;

    float num  = s_start[cur] + __shfl_sync(gmask, em, cur, 8);
    int   prev = cur;

    // ---- t = 1 .. L-1 ----
    for (int t = 1; t < CRF_L; t++) {
        tag = tg_base[t * tstride];
        if (tag == 0) break;               // prefix mask: sequence ended
        em  = em_base[t * CRF_T + j];
        cur = tag - 1;

        // numerator: trans[prev][cur] + em[t][cur]
        num += s_trans[prev * CRF_T + cur] + __shfl_sync(gmask, em, cur, 8);
        prev = cur;

        // gather all 8 betas of my group (values BEFORE update)
        float b0 = __shfl_sync(gmask, beta, 0, 8);
        float b1 = __shfl_sync(gmask, beta, 1, 8);
        float b2 = __shfl_sync(gmask, beta, 2, 8);
        float b3 = __shfl_sync(gmask, beta, 3, 8);
        float b4 = __shfl_sync(gmask, beta, 4, 8);
        float b5 = __shfl_sync(gmask, beta, 5, 8);
        float b6 = __shfl_sync(gmask, beta, 6, 8);
        float b7 = __shfl_sync(gmask, beta, 7, 8);

        // s_j = sum_i beta_i * E[i][j]  (two accumulator chains for ILP)
        float sA = b0 * Ecol[0];
        float sB = b1 * Ecol[1];
        sA = fmaf(b2, Ecol[2], sA);
        sB = fmaf(b3, Ecol[3], sB);
        sA = fmaf(b4, Ecol[4], sA);
        sB = fmaf(b5, Ecol[5], sB);
        sA = fmaf(b6, Ecol[6], sA);
        sB = fmaf(b7, Ecol[7], sB);

        float u = (sA + sB) * __expf(em);

        // power-of-two renormalization every 4 steps (exponent-field only;
        // per-step growth <= ~2^13 so 4 steps stay far inside fp32 range)
        if ((t & 3) == 0) {
            float m = u;
            m = fmaxf(m, __shfl_xor_sync(gmask, m, 1, 8));
            m = fmaxf(m, __shfl_xor_sync(gmask, m, 2, 8));
            m = fmaxf(m, __shfl_xor_sync(gmask, m, 4, 8));
            int e = ((__float_as_int(m) >> 23) & 0xFF) - 127;
            eacc += e;
            beta = u * __int_as_float((127 - e) << 23);   // u * 2^-e
        } else {
            beta = u;
        }
    }

    num += s_end[prev];

    // denom = m0 + eacc*ln2 + log( sum_j beta_j * exp(end_j) )
    float w = beta * __expf(s_end[j]);
    w += __shfl_xor_sync(gmask, w, 1, 8);
    w += __shfl_xor_sync(gmask, w, 2, 8);
    w += __shfl_xor_sync(gmask, w, 4, 8);

    float denom = m0 + (float)eacc * 0.693147180559945309f + __logf(w);

    if (j == 0) g_llh[batch] = denom - num;
}

__global__ void crf_reduce_kernel(float* __restrict__ out)
{
    __shared__ double sh[256];
    double s = 0.0;
    for (int i = threadIdx.x; i < CRF_B; i += 256) s += (double)g_llh[i];
    sh[threadIdx.x] = s;
    __syncthreads();
#pragma unroll
    for (int k = 128; k > 0; k >>= 1) {
        if (threadIdx.x < k) sh[threadIdx.x] += sh[threadIdx.x + k];
        __syncthreads();
    }
    if (threadIdx.x == 0) out[0] = (float)(sh[0] / (double)CRF_B);
}

extern "C" void kernel_launch(void* const* d_in, const int* in_sizes, int n_in,
                              void* d_out, int out_size)
{
    const float* emissions   = (const float*)d_in[0];
    const float* transitions = (const float*)d_in[1];
    const float* start_tr    = (const float*)d_in[2];
    const float* end_tr      = (const float*)d_in[3];
    const int*   tagsw       = (const int*)d_in[4];   // 32-bit word view of tags

    // 8 lanes per batch: B*T threads = 16384 -> 128 blocks x 128 threads
    crf_forward_kernel<<<CRF_B * CRF_T / 128, 128>>>(
        emissions, transitions, start_tr, end_tr, tagsw);
    crf_reduce_kernel<<<1, 256>>>((float*)d_out);
}

// round 5
// speedup vs baseline: 5.6394x; 5.6394x over previous
#include <cuda_runtime.h>

// ProteinCRF: batched linear-chain CRF NLL.  B=2048, L=2048, T=8.
//
// d_in[0] emissions  f32 [B,L,T]
// d_in[1] transitions f32 [T,T]
// d_in[2] start_transitions f32 [T]
// d_in[3] end_transitions   f32 [T]
// d_in[4] tags int64-or-int32 [B,L]  (0=pad, 1..T) -- width detected on device
// out: scalar f32 = mean(denom - num)
//
// R4 changes vs R3 (989us):
//  * length via 10-step branchless binary search (prefix mask) -> loop has a
//    KNOWN trip count, no data-dependent break
//  * software pipeline: chunks of 8 steps, double-buffered em/tag prefetch
//    (MLP ~16) so DRAM latency is off the critical path
//  * exp(em) precomputed per chunk (MUFU off the beta chain)
//  * renorm (2x per chunk) computed from the already-gathered b0..b7, only a
//    single multiply lands on the critical path
//  * reduce kernel: 1024 threads + warp shuffles

#define CRF_B 2048
#define CRF_L 2048
#define CRF_T 8

__device__ float g_llh[CRF_B];   // per-batch (denom - num)

__global__ __launch_bounds__(128, 1)
void crf_forward_kernel(const float* __restrict__ emissions,
                        const float* __restrict__ transitions,
                        const float* __restrict__ start_tr,
                        const float* __restrict__ end_tr,
                        const int*   __restrict__ tagsw)   // 32-bit word view
{
    __shared__ float s_trans[CRF_T * CRF_T];
    __shared__ float s_start[CRF_T];
    __shared__ float s_end[CRF_T];

    const int tid = threadIdx.x;
    if (tid < 64)              s_trans[tid]      = transitions[tid];
    if (tid >= 64 && tid < 72) s_start[tid - 64] = start_tr[tid - 64];
    if (tid >= 72 && tid < 80) s_end[tid - 72]   = end_tr[tid - 72];
    __syncthreads();

    // tags int64 vs int32: lengths >= L/2 so tags[0][1] != 0. If int64 (LE),
    // word #1 is the high half of element 0 -> 0. If int32, it's nonzero.
    const int tstride = (tagsw[1] == 0) ? 2 : 1;

    const int lane  = tid & 31;
    const int j     = lane & 7;          // my state
    const unsigned gmask = 0xFFu << (lane & 24);

    const int batch = (blockIdx.x * blockDim.x + tid) >> 3;
    const float* em_base = emissions + (size_t)batch * (CRF_L * CRF_T);
    const int*   tg_base = tagsw + (size_t)batch * CRF_L * tstride;

    // ---- issue t=0..8 loads immediately (overlap with setup + search) ----
    float em0  = em_base[j];
    int   tag0 = tg_base[0];
    float emA[8]; int tgA[8];
#pragma unroll
    for (int k = 0; k < 8; k++) {
        emA[k] = em_base[(1 + k) * CRF_T + j];
        tgA[k] = tg_base[(1 + k) * tstride];
    }

    // E column j: Ecol[i] = exp(trans[i][j])
    float Ecol[CRF_T];
#pragma unroll
    for (int i = 0; i < CRF_T; i++) Ecol[i] = __expf(s_trans[i * CRF_T + j]);

    // ---- length: first zero index in [L/2, L], 10 branchless steps ----
    int lo = CRF_L / 2, hi = CRF_L;
#pragma unroll
    for (int it = 0; it < 10; it++) {
        int mid = (lo + hi) >> 1;
        bool nz = (tg_base[mid * tstride] != 0);
        lo = nz ? mid + 1 : lo;
        hi = nz ? hi : mid;
    }
    const int len = lo;                  // number of valid steps (>= 1024)

    // ---- t = 0 ----
    float a0 = s_start[j] + em0;
    float mx = a0;
    mx = fmaxf(mx, __shfl_xor_sync(gmask, mx, 1, 8));
    mx = fmaxf(mx, __shfl_xor_sync(gmask, mx, 2, 8));
    mx = fmaxf(mx, __shfl_xor_sync(gmask, mx, 4, 8));
    const float m0 = mx;

    float beta = __expf(a0 - m0);
    int   eacc = 0;

    int   cur0 = tag0 - 1;
    float num  = s_start[cur0] + __shfl_sync(gmask, em0, cur0, 8);
    int   prev = cur0;

    // ---- main loop: chunks of 8, double-buffered prefetch ----
    for (int t0 = 1; t0 < len; t0 += 8) {
        // prefetch next chunk (independent LDGs, clamp to stay in-bounds)
        float emB[8]; int tgB[8];
#pragma unroll
        for (int k = 0; k < 8; k++) {
            int tt = t0 + 8 + k;
            tt = (tt < CRF_L) ? tt : (CRF_L - 1);
            emB[k] = em_base[tt * CRF_T + j];
            tgB[k] = tg_base[tt * tstride];
        }

        // emission exps for this chunk (off the beta critical path)
        float ex[8];
#pragma unroll
        for (int k = 0; k < 8; k++) ex[k] = __expf(emA[k]);

#pragma unroll
        for (int k = 0; k < 8; k++) {
            const bool act = (t0 + k) < len;
            const int  cur = (tgA[k] - 1) & 7;      // tag=0 -> masked anyway

            // numerator contribution (independent chain)
            float addn = s_trans[prev * CRF_T + cur]
                       + __shfl_sync(gmask, emA[k], cur, 8);

            // gather group's betas
            float b0 = __shfl_sync(gmask, beta, 0, 8);
            float b1 = __shfl_sync(gmask, beta, 1, 8);
            float b2 = __shfl_sync(gmask, beta, 2, 8);
            float b3 = __shfl_sync(gmask, beta, 3, 8);
            float b4 = __shfl_sync(gmask, beta, 4, 8);
            float b5 = __shfl_sync(gmask, beta, 5, 8);
            float b6 = __shfl_sync(gmask, beta, 6, 8);
            float b7 = __shfl_sync(gmask, beta, 7, 8);

            // s_j = sum_i b_i * E[i][j]  (two chains for ILP)
            float sA = b0 * Ecol[0];
            float sB = b1 * Ecol[1];
            sA = fmaf(b2, Ecol[2], sA);
            sB = fmaf(b3, Ecol[3], sB);
            sA = fmaf(b4, Ecol[4], sA);
            sB = fmaf(b5, Ecol[5], sB);
            sA = fmaf(b6, Ecol[6], sA);
            sB = fmaf(b7, Ecol[7], sB);

            float u = (sA + sB) * ex[k];

            // renorm 2x per chunk: exponent of max(old betas); fmax tree runs
            // parallel to the FMA chains, only the scale-mul hits the chain.
            if (k == 3 || k == 7) {
                float m = fmaxf(fmaxf(fmaxf(b0, b1), fmaxf(b2, b3)),
                                fmaxf(fmaxf(b4, b5), fmaxf(b6, b7)));
                int e = ((__float_as_int(m) >> 23) & 0xFF) - 127;
                u *= __int_as_float((127 - e) << 23);   // u * 2^-e
                if (act) eacc += e;
            }

            if (act) { beta = u; num += addn; prev = cur; }
        }

#pragma unroll
        for (int k = 0; k < 8; k++) { emA[k] = emB[k]; tgA[k] = tgB[k]; }
    }

    num += s_end[prev];

    // denom = m0 + eacc*ln2 + log( sum_j beta_j * exp(end_j) )
    float w = beta * __expf(s_end[j]);
    w += __shfl_xor_sync(gmask, w, 1, 8);
    w += __shfl_xor_sync(gmask, w, 2, 8);
    w += __shfl_xor_sync(gmask, w, 4, 8);

    float denom = m0 + (float)eacc * 0.693147180559945309f + __logf(w);

    if (j == 0) g_llh[batch] = denom - num;
}

__global__ __launch_bounds__(1024)
void crf_reduce_kernel(float* __restrict__ out)
{
    __shared__ double sh[32];
    const int t    = threadIdx.x;
    const int lane = t & 31;
    const int wrp  = t >> 5;

    double s = (double)g_llh[t] + (double)g_llh[t + 1024];
#pragma unroll
    for (int off = 16; off > 0; off >>= 1)
        s += __shfl_down_sync(0xFFFFFFFFu, s, off);
    if (lane == 0) sh[wrp] = s;
    __syncthreads();

    if (wrp == 0) {
        s = sh[lane];
#pragma unroll
        for (int off = 16; off > 0; off >>= 1)
            s += __shfl_down_sync(0xFFFFFFFFu, s, off);
        if (lane == 0) out[0] = (float)(s / (double)CRF_B);
    }
}

extern "C" void kernel_launch(void* const* d_in, const int* in_sizes, int n_in,
                              void* d_out, int out_size)
{
    const float* emissions   = (const float*)d_in[0];
    const float* transitions = (const float*)d_in[1];
    const float* start_tr    = (const float*)d_in[2];
    const float* end_tr      = (const float*)d_in[3];
    const int*   tagsw       = (const int*)d_in[4];

    crf_forward_kernel<<<CRF_B * CRF_T / 128, 128>>>(
        emissions, transitions, start_tr, end_tr, tagsw);
    crf_reduce_kernel<<<1, 1024>>>((float*)d_out);
}